// round 13
// baseline (speedup 1.0000x reference)
#include <cuda_runtime.h>
#include <cuda_fp16.h>
#include <cstdint>

#define NTHR 256
#define MT 64
#define BSZ 131072
#define NMAT 36
#define GRP_SLABS 72         // per group: 18 mats x 4 slabs (K=64 each)
#define SLAB_HALVES 16384
#define SLAB_BYTES 32768
#define STR2 72              // half2 words per act row; 72 mod 32 = 8 -> conflict-free

// smem byte offsets
#define OFF_WBUF 0                      // [2 groups][2 bufs][32KB]
#define OFF_ACT  131072                 // [2 groups][36864]
#define OFF_BIAS 204800                 // [2 groups][2][256] floats
#define OFF_W1S  208896                 // [2 groups][256] floats
#define OFF_B1S  210944
#define OFF_W5S  212992
#define OFF_XV   215040                 // 64 x 2 floats
#define OFF_PP   215552                 // [2 groups][4][64] floats
#define OFF_SARR 217600
#define OFF_TARR 217856
#define SMEM_DYN 218112

__device__ __half g_wpack[NMAT * 65536];

// ---------------------------------------------------------------------------
__device__ __forceinline__ void cpasync16(uint32_t dst, const void* src) {
    asm volatile("cp.async.cg.shared.global [%0], [%1], 16;" :: "r"(dst), "l"(src));
}
__device__ __forceinline__ void mma_f16(float acc[4], uint4 a, uint32_t b0, uint32_t b1) {
    asm volatile(
        "mma.sync.aligned.m16n8k16.row.col.f32.f16.f16.f32 "
        "{%0,%1,%2,%3}, {%4,%5,%6,%7}, {%8,%9}, {%0,%1,%2,%3};"
        : "+f"(acc[0]), "+f"(acc[1]), "+f"(acc[2]), "+f"(acc[3])
        : "r"(a.x), "r"(a.y), "r"(a.z), "r"(a.w), "r"(b0), "r"(b1));
}
__device__ __forceinline__ uint32_t h2u(float lo, float hi) {
    __half2 h = __floats2half2_rn(lo, hi);
    return *(uint32_t*)&h;
}
#define GBAR() asm volatile("bar.sync %0, 128;" :: "r"(grp + 1) : "memory")

// ---------------------------------------------------------------------------
// prepack: W[k][n] fp32 -> fp16, A-fragment order for m16n8k16 with
// k-permutation kappa (pairs (j, j+8) within each 16-block). Slab = K=64.
// mat = ((st*6 + layer)*3 + g)
// ---------------------------------------------------------------------------
__global__ void prepack_kernel(const float* sW2, const float* sW3, const float* sW4,
                               const float* tW2, const float* tW3, const float* tW4) {
    int idx = blockIdx.x * blockDim.x + threadIdx.x;
    if (idx >= NMAT * 8192) return;
    int lane = idx & 31;
    int mt   = (idx >> 5) & 15;
    int kc   = (idx >> 9) & 3;
    int slab = (idx >> 11) & 3;
    int mat  = idx >> 13;

    int st = mat / 18, rem = mat % 18, l = rem / 3, g = rem % 3;
    const float* src;
    switch (st * 3 + g) {
        case 0: src = sW2; break;
        case 1: src = sW3; break;
        case 2: src = sW4; break;
        case 3: src = tW2; break;
        case 4: src = tW3; break;
        default: src = tW4; break;
    }
    src += l * 65536;

    int v = lane & 3, mlow = lane >> 2;
    int kb = slab * 64 + kc * 16;
    int nb = mt * 16;

    uint4 o;
    o.x = h2u(src[(kb + v)     * 256 + nb + mlow],     src[(kb + v + 8)  * 256 + nb + mlow]);
    o.y = h2u(src[(kb + v)     * 256 + nb + mlow + 8], src[(kb + v + 8)  * 256 + nb + mlow + 8]);
    o.z = h2u(src[(kb + v + 4) * 256 + nb + mlow],     src[(kb + v + 12) * 256 + nb + mlow]);
    o.w = h2u(src[(kb + v + 4) * 256 + nb + mlow + 8], src[(kb + v + 12) * 256 + nb + mlow + 8]);

    *(uint4*)(g_wpack + (size_t)mat * 65536 + slab * SLAB_HALVES
              + ((kc * 16 + mt) * 32 + lane) * 8) = o;
}

// ---------------------------------------------------------------------------
// Fused kernel: one CTA = 64 samples; warps 0-3 run the s-net chain, warps
// 4-7 run the t-net chain concurrently (independent rings, acts, barriers).
// ---------------------------------------------------------------------------
__global__ void __launch_bounds__(NTHR, 1)
realnvp_kernel(const float* __restrict__ X,
               const float* __restrict__ sW1, const float* __restrict__ sB1,
               const float* __restrict__ sB2, const float* __restrict__ sB3,
               const float* __restrict__ sB4, const float* __restrict__ sW5,
               const float* __restrict__ sB5,
               const float* __restrict__ tW1, const float* __restrict__ tB1,
               const float* __restrict__ tB2, const float* __restrict__ tB3,
               const float* __restrict__ tB4, const float* __restrict__ tW5,
               const float* __restrict__ tB5,
               float* __restrict__ out) {
    extern __shared__ char base[];
    int tid  = threadIdx.x;
    int grp  = tid >> 7;                  // 0 = s-net, 1 = t-net
    int tg   = tid & 127;                 // thread id within group
    int wid  = tg >> 5;                   // 0..3 feature tile of 64
    int lane = tid & 31;
    int u    = lane >> 2;                 // 0..7
    int v    = lane & 3;                  // 0..3
    int gbase = blockIdx.x * MT;

    uint32_t* actg  = (uint32_t*)(base + OFF_ACT + grp * 36864);
    float*  bias2   = (float*)(base + OFF_BIAS) + grp * 512;   // [2][256]
    float*  w1s     = (float*)(base + OFF_W1S) + grp * 256;
    float*  b1s     = (float*)(base + OFF_B1S) + grp * 256;
    float*  w5sg    = (float*)(base + OFF_W5S) + grp * 256;
    float*  xv      = (float*)(base + OFF_XV);
    float*  ppg     = (float*)(base + OFF_PP) + grp * 256;     // [4][64]
    float*  sarr    = (float*)(base + OFF_SARR);
    float*  tarr    = (float*)(base + OFF_TARR);
    uint32_t wbuf_g = (uint32_t)__cvta_generic_to_shared(base + OFF_WBUF)
                      + (uint32_t)grp * 65536;

    // group-specific parameter set
    const float *W1, *B1, *B2, *B3, *B4, *W5, *B5;
    if (grp == 0) { W1 = sW1; B1 = sB1; B2 = sB2; B3 = sB3; B4 = sB4; W5 = sW5; B5 = sB5; }
    else          { W1 = tW1; B1 = tB1; B2 = tB2; B3 = tB3; B4 = tB4; W5 = tW5; B5 = tB5; }

    // hoisted bases
    const uint32_t* actu_b = actg + v * STR2 + u;          // B-frag base
    const int a_off = (wid * 4) * 32 * 8 + lane * 8;       // A-frag half-offset base

    float ldet = 0.f;
    if (tid < MT) {
        float2 xx = *(const float2*)&X[(gbase + tid) * 2];
        xv[tid * 2 + 0] = logf(xx.x / (1.f - xx.x));
        xv[tid * 2 + 1] = logf(xx.y / (1.f - xx.y));
    }
    __syncthreads();                      // xv visible to both groups

    // ---- per-group weight slab prefetch (2-buffer ring of 32KB) ----
    // group slab sequence: 18 mats (layer 5..0, within layer W2,W3,W4) x 4 slabs
    auto prefetch = [&](int q) {
        int qq = (q >= GRP_SLABS) ? q - GRP_SLABS : q;
        int j = qq >> 2, sl = qq & 3;
        int li = 5 - j / 3;
        int gi = j % 3;
        int mat = (grp * 6 + li) * 3 + gi;
        const __half* src = g_wpack + (size_t)mat * 65536 + sl * SLAB_HALVES + tg * 8;
        uint32_t dst = wbuf_g + (uint32_t)(q & 1) * SLAB_BYTES + tg * 16;
#pragma unroll
        for (int it = 0; it < 16; it++)
            cpasync16(dst + it * 2048, src + it * 1024);
        asm volatile("cp.async.commit_group;");
    };

    prefetch(0);

    // ---- layer0: thread = one k-pair row (128 rows), 64 samples each ----
    auto layer0 = [&](const float* w1row, const float* b1, int cdim) {
        w1s[tg] = w1row[tg]; w1s[tg + 128] = w1row[tg + 128];
        b1s[tg] = b1[tg];    b1s[tg + 128] = b1[tg + 128];
        GBAR();
        int r = tg;
        int k0 = ((r >> 3) << 4) + (r & 7), k1 = k0 + 8;
        float w0 = w1s[k0], bb0 = b1s[k0];
        float w1v = w1s[k1], bb1 = b1s[k1];
#pragma unroll 4
        for (int i = 0; i < 16; i++) {
            uint4 wrds;
            int s = i * 4;
            float x0 = xv[(s + 0) * 2 + cdim], x1 = xv[(s + 1) * 2 + cdim];
            float x2 = xv[(s + 2) * 2 + cdim], x3 = xv[(s + 3) * 2 + cdim];
            wrds.x = h2u(fmaxf(fmaf(x0, w0, bb0), 0.f), fmaxf(fmaf(x0, w1v, bb1), 0.f));
            wrds.y = h2u(fmaxf(fmaf(x1, w0, bb0), 0.f), fmaxf(fmaf(x1, w1v, bb1), 0.f));
            wrds.z = h2u(fmaxf(fmaf(x2, w0, bb0), 0.f), fmaxf(fmaf(x2, w1v, bb1), 0.f));
            wrds.w = h2u(fmaxf(fmaf(x3, w0, bb0), 0.f), fmaxf(fmaf(x3, w1v, bb1), 0.f));
            *(uint4*)&actg[r * STR2 + s] = wrds;
        }
        // no trailing bar: next gemm's first slab-bar covers act visibility
    };

    // ---- one 64x256 @ 256x256 GEMM per group; warp tile m64 x n64 ----
    auto gemm = [&](int gc, const float* biasg, bool fuse,
                    const float* w5col, float b5) {
        float* bias_c = bias2 + (gc & 1) * 256;
        bias_c[tg] = biasg[tg];
        bias_c[tg + 128] = biasg[tg + 128];
        if (fuse) { w5sg[tg] = w5col[tg * 2]; w5sg[tg + 128] = w5col[(tg + 128) * 2]; }

        float acc[4][8][4];
#pragma unroll
        for (int a = 0; a < 4; a++)
#pragma unroll
            for (int b = 0; b < 8; b++)
#pragma unroll
                for (int q = 0; q < 4; q++) acc[a][b][q] = 0.f;

#pragma unroll 1
        for (int sl = 0; sl < 4; sl++) {
            int q = gc * 4 + sl;
            asm volatile("cp.async.wait_group 0;");
            GBAR();                      // slab q visible in group; buf (q+1)&1 free
            prefetch(q + 1);
            const __half* wb = (const __half*)(base + OFF_WBUF + grp * 65536
                                               + (q & 1) * SLAB_BYTES);
#pragma unroll
            for (int kc = 0; kc < 4; kc++) {
                uint4 a[4];
#pragma unroll
                for (int mf = 0; mf < 4; mf++)
                    a[mf] = *(const uint4*)(wb + a_off + (kc * 16 * 32 + mf * 32) * 8);
                int kg = sl * 4 + kc;
                const uint32_t* p0 = actu_b + kg * 8 * STR2;
                uint32_t b0[8], b1[8];
#pragma unroll
                for (int nf = 0; nf < 8; nf++) {
                    b0[nf] = p0[nf * 8];
                    b1[nf] = p0[4 * STR2 + nf * 8];
                }
#pragma unroll
                for (int mf = 0; mf < 4; mf++)
#pragma unroll
                    for (int nf = 0; nf < 8; nf++)
                        mma_f16(acc[mf][nf], a[mf], b0[nf], b1[nf]);
            }
        }
        GBAR();                          // all reads of act done before overwrite

        if (!fuse) {
            // bias + relu + fp16 pair store; row = (wid*4+mf)*8+u holds (f0, f0+8)
#pragma unroll
            for (int mf = 0; mf < 4; mf++) {
                int f0 = wid * 64 + mf * 16 + u;
                int row = (wid * 4 + mf) * 8 + u;
                float bx = bias_c[f0], by = bias_c[f0 + 8];
#pragma unroll
                for (int nf = 0; nf < 8; nf++) {
                    int s0 = nf * 8 + v * 2;
                    uint2 wr;
                    wr.x = h2u(fmaxf(acc[mf][nf][0] + bx, 0.f),
                               fmaxf(acc[mf][nf][2] + by, 0.f));
                    wr.y = h2u(fmaxf(acc[mf][nf][1] + bx, 0.f),
                               fmaxf(acc[mf][nf][3] + by, 0.f));
                    *(uint2*)&actg[row * STR2 + s0] = wr;
                }
            }
            // no trailing bar (bias double-buffered; act covered by next slab-bar)
        } else {
            // fused H->1 dot
            float p[8][2];
#pragma unroll
            for (int nf = 0; nf < 8; nf++) { p[nf][0] = 0.f; p[nf][1] = 0.f; }
#pragma unroll
            for (int mf = 0; mf < 4; mf++) {
                int f0 = wid * 64 + mf * 16 + u;
                float bx = bias_c[f0], by = bias_c[f0 + 8];
                float wa = w5sg[f0],  wb5 = w5sg[f0 + 8];
#pragma unroll
                for (int nf = 0; nf < 8; nf++) {
                    float v0 = fmaxf(acc[mf][nf][0] + bx, 0.f);
                    float v1 = fmaxf(acc[mf][nf][1] + bx, 0.f);
                    float v2 = fmaxf(acc[mf][nf][2] + by, 0.f);
                    float v3 = fmaxf(acc[mf][nf][3] + by, 0.f);
                    p[nf][0] = fmaf(v0, wa, fmaf(v2, wb5, p[nf][0]));
                    p[nf][1] = fmaf(v1, wa, fmaf(v3, wb5, p[nf][1]));
                }
            }
#pragma unroll
            for (int nf = 0; nf < 8; nf++) {
#pragma unroll
                for (int j = 0; j < 2; j++) {
                    float t = p[nf][j];
                    t += __shfl_down_sync(0xffffffffu, t, 16);
                    t += __shfl_down_sync(0xffffffffu, t, 8);
                    t += __shfl_down_sync(0xffffffffu, t, 4);
                    if (lane < 4)
                        ppg[wid * 64 + nf * 8 + lane * 2 + j] = t;
                }
            }
            GBAR();
            if (tg < MT) {
                float o = ppg[tg] + ppg[64 + tg] + ppg[128 + tg] + ppg[192 + tg] + b5;
                if (grp == 0) sarr[tg] = tanhf(o);
                else          tarr[tg] = o;
            }
        }
    };

    // ---- main flow: 6 coupling layers, reversed; s and t chains in parallel ----
    int gc = 0;
    for (int i = 5; i >= 0; i--) {
        int cdim = (i & 1) ? 0 : 1;
        int other = 1 - cdim;

        layer0(W1 + i * 512 + cdim * 256, B1 + i * 256, cdim);
        gemm(gc++, B2 + i * 256, false, 0, 0.f);
        gemm(gc++, B3 + i * 256, false, 0, 0.f);
        gemm(gc++, B4 + i * 256, true, W5 + i * 512 + other, B5[i * 2 + other]);

        __syncthreads();                 // sarr (grp0) + tarr (grp1) both visible
        if (tid < MT) {
            float sv = sarr[tid], tv = tarr[tid];
            xv[tid * 2 + other] = (xv[tid * 2 + other] - tv) * expf(-sv);
            ldet -= sv;
        }
        __syncthreads();                 // xv visible to both groups' next layer0
    }

    if (tid < MT) {
        int g = gbase + tid;
        float2 o;
        o.x = 1.f / (1.f + expf(-xv[tid * 2 + 0]));
        o.y = 1.f / (1.f + expf(-xv[tid * 2 + 1]));
        *(float2*)&out[g * 2] = o;
        out[2 * BSZ + g] = ldet;
    }
    asm volatile("cp.async.wait_group 0;");
}

// ---------------------------------------------------------------------------
extern "C" void kernel_launch(void* const* d_in, const int* in_sizes, int n_in,
                              void* d_out, int out_size) {
    const float* X   = (const float*)d_in[0];
    const float* sW1 = (const float*)d_in[1];
    const float* sB1 = (const float*)d_in[2];
    const float* sW2 = (const float*)d_in[3];
    const float* sB2 = (const float*)d_in[4];
    const float* sW3 = (const float*)d_in[5];
    const float* sB3 = (const float*)d_in[6];
    const float* sW4 = (const float*)d_in[7];
    const float* sB4 = (const float*)d_in[8];
    const float* sW5 = (const float*)d_in[9];
    const float* sB5 = (const float*)d_in[10];
    const float* tW1 = (const float*)d_in[11];
    const float* tB1 = (const float*)d_in[12];
    const float* tW2 = (const float*)d_in[13];
    const float* tB2 = (const float*)d_in[14];
    const float* tW3 = (const float*)d_in[15];
    const float* tB3 = (const float*)d_in[16];
    const float* tW4 = (const float*)d_in[17];
    const float* tB4 = (const float*)d_in[18];
    const float* tW5 = (const float*)d_in[19];
    const float* tB5 = (const float*)d_in[20];

    cudaFuncSetAttribute(realnvp_kernel, cudaFuncAttributeMaxDynamicSharedMemorySize,
                         SMEM_DYN);

    prepack_kernel<<<(NMAT * 8192 + 255) / 256, 256>>>(sW2, sW3, sW4, tW2, tW3, tW4);
    realnvp_kernel<<<BSZ / MT, NTHR, SMEM_DYN>>>(
        X, sW1, sB1, sB2, sB3, sB4, sW5, sB5,
        tW1, tB1, tB2, tB3, tB4, tW5, tB5, (float*)d_out);
}

// round 14
// speedup vs baseline: 1.0885x; 1.0885x over previous
#include <cuda_runtime.h>
#include <cuda_fp16.h>
#include <cstdint>

#define NTHR 128
#define MT 64
#define BSZ 131072
#define NMAT 36
#define TOTAL_SLABS 144      // 36 mats x 4 slabs (K=64 each)
#define SLAB_HALVES 16384
#define SLAB_BYTES 32768
#define STR2 72              // half2 words per act row; 72 mod 32 = 8 -> conflict-free
#define NPHASE 48

// smem byte offsets
#define OFF_WBUF 0                      // 2 x 32KB
#define OFF_ACT  65536                  // 128 rows x 72 words x 4B = 36864
#define OFF_PBUF 102400                 // 2 x 512 floats (phase-param ping-pong)
#define OFF_XV   106496                 // 64 x 2 floats
#define OFF_PP   107008                 // 4 x 64 floats
#define OFF_SARR 108032
#define OFF_TARR 108288
#define SMEM_DYN 108544

__device__ __half g_wpack[NMAT * 65536];
__device__ float  g_pb[NPHASE * 512];   // per-phase params (prepacked)

// ---------------------------------------------------------------------------
__device__ __forceinline__ void cpasync16(uint32_t dst, const void* src) {
    asm volatile("cp.async.cg.shared.global [%0], [%1], 16;" :: "r"(dst), "l"(src));
}
__device__ __forceinline__ void mma_f16(float acc[4], uint4 a, uint32_t b0, uint32_t b1) {
    asm volatile(
        "mma.sync.aligned.m16n8k16.row.col.f32.f16.f16.f32 "
        "{%0,%1,%2,%3}, {%4,%5,%6,%7}, {%8,%9}, {%0,%1,%2,%3};"
        : "+f"(acc[0]), "+f"(acc[1]), "+f"(acc[2]), "+f"(acc[3])
        : "r"(a.x), "r"(a.y), "r"(a.z), "r"(a.w), "r"(b0), "r"(b1));
}
__device__ __forceinline__ uint32_t h2u(float lo, float hi) {
    __half2 h = __floats2half2_rn(lo, hi);
    return *(uint32_t*)&h;
}

// ---------------------------------------------------------------------------
// prepack weights: W[k][n] fp32 -> fp16, A-fragment order for m16n8k16 with
// k-permutation kappa (pairs (j, j+8) within each 16-block). Slab = K=64.
// ---------------------------------------------------------------------------
__global__ void prepack_kernel(const float* sW2, const float* sW3, const float* sW4,
                               const float* tW2, const float* tW3, const float* tW4) {
    int idx = blockIdx.x * blockDim.x + threadIdx.x;
    if (idx >= NMAT * 8192) return;
    int lane = idx & 31;
    int mt   = (idx >> 5) & 15;
    int kc   = (idx >> 9) & 3;
    int slab = (idx >> 11) & 3;
    int mat  = idx >> 13;

    int st = mat / 18, rem = mat % 18, l = rem / 3, g = rem % 3;
    const float* src;
    switch (st * 3 + g) {
        case 0: src = sW2; break;
        case 1: src = sW3; break;
        case 2: src = sW4; break;
        case 3: src = tW2; break;
        case 4: src = tW3; break;
        default: src = tW4; break;
    }
    src += l * 65536;

    int v = lane & 3, mlow = lane >> 2;
    int kb = slab * 64 + kc * 16;
    int nb = mt * 16;

    uint4 o;
    o.x = h2u(src[(kb + v)     * 256 + nb + mlow],     src[(kb + v + 8)  * 256 + nb + mlow]);
    o.y = h2u(src[(kb + v)     * 256 + nb + mlow + 8], src[(kb + v + 8)  * 256 + nb + mlow + 8]);
    o.z = h2u(src[(kb + v + 4) * 256 + nb + mlow],     src[(kb + v + 12) * 256 + nb + mlow]);
    o.w = h2u(src[(kb + v + 4) * 256 + nb + mlow + 8], src[(kb + v + 12) * 256 + nb + mlow + 8]);

    *(uint4*)(g_wpack + (size_t)mat * 65536 + slab * SLAB_HALVES
              + ((kc * 16 + mt) * 32 + lane) * 8) = o;
}

// ---------------------------------------------------------------------------
// prepack phase params: 48 phases x 512 floats.
// phase p: block=p>>2 (net=block&1, li=5-(block>>1)); within=p&3:
//   0 -> [W1 cdim-row (256) | B1 (256)]
//   1 -> [B2 (256) | 0]
//   2 -> [B3 (256) | 0]
//   3 -> [B4 (256) | W5 'other'-column dense (256)]
// ---------------------------------------------------------------------------
__global__ void prepack_params(const float* sW1, const float* sB1, const float* sB2,
                               const float* sB3, const float* sB4, const float* sW5,
                               const float* tW1, const float* tB1, const float* tB2,
                               const float* tB3, const float* tB4, const float* tW5) {
    int idx = blockIdx.x * blockDim.x + threadIdx.x;
    if (idx >= NPHASE * 512) return;
    int p = idx >> 9, j = idx & 511;
    int blk = p >> 2, within = p & 3;
    int net = blk & 1, li = 5 - (blk >> 1);
    int cdim = (li & 1) ? 0 : 1, other = 1 - cdim;
    const float *W1, *B1, *B2, *B3, *B4, *W5;
    if (net == 0) { W1 = sW1; B1 = sB1; B2 = sB2; B3 = sB3; B4 = sB4; W5 = sW5; }
    else          { W1 = tW1; B1 = tB1; B2 = tB2; B3 = tB3; B4 = tB4; W5 = tW5; }
    float val = 0.f;
    if (within == 0)      val = (j < 256) ? W1[li * 512 + cdim * 256 + j]
                                          : B1[li * 256 + (j - 256)];
    else if (within == 1) { if (j < 256) val = B2[li * 256 + j]; }
    else if (within == 2) { if (j < 256) val = B3[li * 256 + j]; }
    else                  val = (j < 256) ? B4[li * 256 + j]
                                          : W5[li * 512 + (j - 256) * 2 + other];
    g_pb[p * 512 + j] = val;
}

// ---------------------------------------------------------------------------
__global__ void __launch_bounds__(NTHR, 2)
realnvp_kernel(const float* __restrict__ X,
               const float* __restrict__ sB5, const float* __restrict__ tB5,
               float* __restrict__ out) {
    extern __shared__ char base[];
    uint32_t* actu = (uint32_t*)(base + OFF_ACT);     // half2 words [row][STR2]
    float*    pbf  = (float*)(base + OFF_PBUF);       // [2][512] phase params
    float*    xv   = (float*)(base + OFF_XV);
    float*    pp   = (float*)(base + OFF_PP);         // [4][64]
    float*    sarr = (float*)(base + OFF_SARR);
    float*    tarr = (float*)(base + OFF_TARR);
    uint32_t  wbuf_sh = (uint32_t)__cvta_generic_to_shared(base + OFF_WBUF);
    uint32_t  pbuf_sh = (uint32_t)__cvta_generic_to_shared(base + OFF_PBUF);

    int tid  = threadIdx.x;
    int wid  = tid >> 5, lane = tid & 31;     // wid = feature tile of 64 (0..3)
    int u    = lane >> 2;                     // 0..7
    int v    = lane & 3;                      // 0..3
    int gbase = blockIdx.x * MT;

    // hoisted loop-invariant bases
    const uint32_t* actu_b = actu + v * STR2 + u;          // B-frag base
    const int a_off = (wid * 4) * 32 * 8 + lane * 8;       // A-frag half-offset base

    // ---- phase-param prefetch: 2KB into pbuf[(p&1)] ----
    auto pf_params = [&](int p) {
        if (p >= NPHASE) return;
        cpasync16(pbuf_sh + (uint32_t)(p & 1) * 2048 + tid * 16,
                  g_pb + p * 512 + tid * 4);
    };

    // ---- weight slab prefetch (2-buffer ring of 32KB; 256B per thread) ----
    auto prefetch = [&](int q) {
        int qq = (q >= TOTAL_SLABS) ? q - TOTAL_SLABS : q;
        int j = qq >> 2, sl = qq & 3;
        int li = 5 - j / 6;
        int r6 = j % 6;
        int mat = ((r6 / 3) * 6 + li) * 3 + (r6 % 3);
        const __half* src = g_wpack + (size_t)mat * 65536 + sl * SLAB_HALVES + tid * 8;
        uint32_t dst = wbuf_sh + (uint32_t)(q & 1) * SLAB_BYTES + tid * 16;
#pragma unroll
        for (int it = 0; it < 16; it++)
            cpasync16(dst + it * 2048, src + it * 1024);
        asm volatile("cp.async.commit_group;");
    };

    float ldet = 0.f;
    if (tid < MT) {
        float2 xx = *(const float2*)&X[(gbase + tid) * 2];
        xv[tid * 2 + 0] = logf(xx.x / (1.f - xx.x));
        xv[tid * 2 + 1] = logf(xx.y / (1.f - xx.y));
    }

    pf_params(0);        // joins prefetch(0)'s commit group
    prefetch(0);
    asm volatile("cp.async.wait_group 0;");
    __syncthreads();     // phase-0 params + slab 0 + xv visible

    // ---- layer0: thread = one k-pair row (128 rows), 64 samples each ----
    auto layer0 = [&](int ph, int cdim) {
        pf_params(ph + 1);               // safe: all threads past previous phase
        const float* pb = pbf + (ph & 1) * 512;
        int r = tid;
        int k0 = ((r >> 3) << 4) + (r & 7), k1 = k0 + 8;
        float w0 = pb[k0],       bb0 = pb[256 + k0];
        float w1v = pb[k1],      bb1 = pb[256 + k1];
#pragma unroll 4
        for (int i = 0; i < 16; i++) {
            uint4 wrds;
            int s = i * 4;
            float x0 = xv[(s + 0) * 2 + cdim], x1 = xv[(s + 1) * 2 + cdim];
            float x2 = xv[(s + 2) * 2 + cdim], x3 = xv[(s + 3) * 2 + cdim];
            wrds.x = h2u(fmaxf(fmaf(x0, w0, bb0), 0.f), fmaxf(fmaf(x0, w1v, bb1), 0.f));
            wrds.y = h2u(fmaxf(fmaf(x1, w0, bb0), 0.f), fmaxf(fmaf(x1, w1v, bb1), 0.f));
            wrds.z = h2u(fmaxf(fmaf(x2, w0, bb0), 0.f), fmaxf(fmaf(x2, w1v, bb1), 0.f));
            wrds.w = h2u(fmaxf(fmaf(x3, w0, bb0), 0.f), fmaxf(fmaf(x3, w1v, bb1), 0.f));
            *(uint4*)&actu[r * STR2 + s] = wrds;
        }
        // no trailing sync: next gemm's first slab-sync covers act visibility
    };

    // ---- one 64x256 @ 256x256 GEMM; warp tile m64(features) x n64(samples) ----
    auto gemm = [&](int gc, int ph, bool fuse, float b5, bool is_s) {
        const float* pb = pbf + (ph & 1) * 512;

        float acc[4][8][4];
#pragma unroll
        for (int a = 0; a < 4; a++)
#pragma unroll
            for (int b = 0; b < 8; b++)
#pragma unroll
                for (int q = 0; q < 4; q++) acc[a][b][q] = 0.f;

#pragma unroll 1
        for (int sl = 0; sl < 4; sl++) {
            int q = gc * 4 + sl;
            asm volatile("cp.async.wait_group 0;");
            __syncthreads();         // slab q visible; buf (q+1)&1 free; act ready
            if (sl == 0) pf_params(ph + 1);   // all threads past phase ph-1
            prefetch(q + 1);
            const __half* wb = (const __half*)(base + OFF_WBUF + (q & 1) * SLAB_BYTES);
#pragma unroll
            for (int kc = 0; kc < 4; kc++) {
                uint4 a[4];
#pragma unroll
                for (int mf = 0; mf < 4; mf++)
                    a[mf] = *(const uint4*)(wb + a_off + (kc * 16 * 32 + mf * 32) * 8);
                int kg = sl * 4 + kc;
                const uint32_t* p0 = actu_b + kg * 8 * STR2;
                uint32_t b0[8], b1[8];
#pragma unroll
                for (int nf = 0; nf < 8; nf++) {
                    b0[nf] = p0[nf * 8];
                    b1[nf] = p0[4 * STR2 + nf * 8];
                }
#pragma unroll
                for (int mf = 0; mf < 4; mf++)
#pragma unroll
                    for (int nf = 0; nf < 8; nf++)
                        mma_f16(acc[mf][nf], a[mf], b0[nf], b1[nf]);
            }
        }
        __syncthreads();                 // all reads of act done before overwrite

        if (!fuse) {
            // bias + relu + fp16 pair store; row = (wid*4+mf)*8+u holds (f0, f0+8)
#pragma unroll
            for (int mf = 0; mf < 4; mf++) {
                int f0 = wid * 64 + mf * 16 + u;
                int row = (wid * 4 + mf) * 8 + u;
                float bx = pb[f0], by = pb[f0 + 8];
#pragma unroll
                for (int nf = 0; nf < 8; nf++) {
                    int s0 = nf * 8 + v * 2;
                    uint2 wr;
                    wr.x = h2u(fmaxf(acc[mf][nf][0] + bx, 0.f),
                               fmaxf(acc[mf][nf][2] + by, 0.f));
                    wr.y = h2u(fmaxf(acc[mf][nf][1] + bx, 0.f),
                               fmaxf(acc[mf][nf][3] + by, 0.f));
                    *(uint2*)&actu[row * STR2 + s0] = wr;
                }
            }
            // no trailing sync (params ping-ponged; act covered by next slab-sync)
        } else {
            // fused H->1 dot: p[s] = sum_f relu(acc+bias) * w5[f]
            float p[8][2];
#pragma unroll
            for (int nf = 0; nf < 8; nf++) { p[nf][0] = 0.f; p[nf][1] = 0.f; }
#pragma unroll
            for (int mf = 0; mf < 4; mf++) {
                int f0 = wid * 64 + mf * 16 + u;
                float bx = pb[f0],       by = pb[f0 + 8];
                float wa = pb[256 + f0], wb5 = pb[256 + f0 + 8];
#pragma unroll
                for (int nf = 0; nf < 8; nf++) {
                    float v0 = fmaxf(acc[mf][nf][0] + bx, 0.f);
                    float v1 = fmaxf(acc[mf][nf][1] + bx, 0.f);
                    float v2 = fmaxf(acc[mf][nf][2] + by, 0.f);
                    float v3 = fmaxf(acc[mf][nf][3] + by, 0.f);
                    p[nf][0] = fmaf(v0, wa, fmaf(v2, wb5, p[nf][0]));
                    p[nf][1] = fmaf(v1, wa, fmaf(v3, wb5, p[nf][1]));
                }
            }
#pragma unroll
            for (int nf = 0; nf < 8; nf++) {
#pragma unroll
                for (int j = 0; j < 2; j++) {
                    float t = p[nf][j];
                    t += __shfl_down_sync(0xffffffffu, t, 16);
                    t += __shfl_down_sync(0xffffffffu, t, 8);
                    t += __shfl_down_sync(0xffffffffu, t, 4);
                    if (lane < 4)
                        pp[wid * 64 + nf * 8 + lane * 2 + j] = t;
                }
            }
            __syncthreads();
            if (tid < MT) {
                float o = pp[tid] + pp[64 + tid] + pp[128 + tid] + pp[192 + tid] + b5;
                if (is_s) sarr[tid] = tanhf(o);
                else      tarr[tid] = o;
            }
        }
    };

    // ---- main flow: 6 coupling layers, reversed ----
    int gc = 0, ph = 0;
    for (int i = 5; i >= 0; i--) {
        int cdim = (i & 1) ? 0 : 1;
        int other = 1 - cdim;
        float b5s = sB5[i * 2 + other];
        float b5t = tB5[i * 2 + other];

        layer0(ph++, cdim);
        gemm(gc++, ph++, false, 0.f, false);
        gemm(gc++, ph++, false, 0.f, false);
        gemm(gc++, ph++, true, b5s, true);

        layer0(ph++, cdim);
        gemm(gc++, ph++, false, 0.f, false);
        gemm(gc++, ph++, false, 0.f, false);
        gemm(gc++, ph++, true, b5t, false);

        // coupling update (same-tid as sarr/tarr writers; no sync needed)
        if (tid < MT) {
            float sv = sarr[tid], tv = tarr[tid];
            xv[tid * 2 + other] = (xv[tid * 2 + other] - tv) * expf(-sv);
            ldet -= sv;
        }
        __syncthreads();    // xv visible to next layer0 / output
    }

    if (tid < MT) {
        int g = gbase + tid;
        float2 o;
        o.x = 1.f / (1.f + expf(-xv[tid * 2 + 0]));
        o.y = 1.f / (1.f + expf(-xv[tid * 2 + 1]));
        *(float2*)&out[g * 2] = o;
        out[2 * BSZ + g] = ldet;
    }
    asm volatile("cp.async.wait_group 0;");
}

// ---------------------------------------------------------------------------
extern "C" void kernel_launch(void* const* d_in, const int* in_sizes, int n_in,
                              void* d_out, int out_size) {
    const float* X   = (const float*)d_in[0];
    const float* sW1 = (const float*)d_in[1];
    const float* sB1 = (const float*)d_in[2];
    const float* sW2 = (const float*)d_in[3];
    const float* sB2 = (const float*)d_in[4];
    const float* sW3 = (const float*)d_in[5];
    const float* sB3 = (const float*)d_in[6];
    const float* sW4 = (const float*)d_in[7];
    const float* sB4 = (const float*)d_in[8];
    const float* sW5 = (const float*)d_in[9];
    const float* sB5 = (const float*)d_in[10];
    const float* tW1 = (const float*)d_in[11];
    const float* tB1 = (const float*)d_in[12];
    const float* tW2 = (const float*)d_in[13];
    const float* tB2 = (const float*)d_in[14];
    const float* tW3 = (const float*)d_in[15];
    const float* tB3 = (const float*)d_in[16];
    const float* tW4 = (const float*)d_in[17];
    const float* tB4 = (const float*)d_in[18];
    const float* tW5 = (const float*)d_in[19];
    const float* tB5 = (const float*)d_in[20];

    cudaFuncSetAttribute(realnvp_kernel, cudaFuncAttributeMaxDynamicSharedMemorySize,
                         SMEM_DYN);

    prepack_kernel<<<(NMAT * 8192 + 255) / 256, 256>>>(sW2, sW3, sW4, tW2, tW3, tW4);
    prepack_params<<<(NPHASE * 512 + 255) / 256, 256>>>(
        sW1, sB1, sB2, sB3, sB4, sW5, tW1, tB1, tB2, tB3, tB4, tW5);
    realnvp_kernel<<<BSZ / MT, NTHR, SMEM_DYN>>>(X, sB5, tB5, (float*)d_out);
}

// round 15
// speedup vs baseline: 1.2281x; 1.1282x over previous
#include <cuda_runtime.h>
#include <cuda_fp16.h>
#include <cstdint>

#define NTHR 128
#define MT 64
#define BSZ 131072
#define NMAT 36
#define NPHASE 48
#define STR2 72              // half2 words per act row; 72 mod 32 = 8 -> conflict-free

// smem byte offsets (no weight ring anymore)
#define OFF_ACT  0                      // 128 rows x 72 words x 4B = 36864
#define OFF_PBUF 36864                  // 2 x 512 floats (phase-param ping-pong)
#define OFF_XV   40960                  // 64 x 2 floats
#define OFF_PP   41472                  // 4 x 64 floats
#define OFF_SARR 42496
#define OFF_TARR 42752
#define SMEM_DYN 43008

__device__ __half g_wpack[NMAT * 65536];
__device__ float  g_pb[NPHASE * 512];   // per-phase params (prepacked)

// ---------------------------------------------------------------------------
__device__ __forceinline__ void cpasync16(uint32_t dst, const void* src) {
    asm volatile("cp.async.cg.shared.global [%0], [%1], 16;" :: "r"(dst), "l"(src));
}
__device__ __forceinline__ void mma_f16(float acc[4], uint4 a, uint32_t b0, uint32_t b1) {
    asm volatile(
        "mma.sync.aligned.m16n8k16.row.col.f32.f16.f16.f32 "
        "{%0,%1,%2,%3}, {%4,%5,%6,%7}, {%8,%9}, {%0,%1,%2,%3};"
        : "+f"(acc[0]), "+f"(acc[1]), "+f"(acc[2]), "+f"(acc[3])
        : "r"(a.x), "r"(a.y), "r"(a.z), "r"(a.w), "r"(b0), "r"(b1));
}
__device__ __forceinline__ uint32_t h2u(float lo, float hi) {
    __half2 h = __floats2half2_rn(lo, hi);
    return *(uint32_t*)&h;
}

// ---------------------------------------------------------------------------
// prepack weights: W[k][n] fp32 -> fp16, A-fragment order for m16n8k16 with
// k-permutation kappa (pairs (j, j+8) within each 16-block).
// Flat layout: frag f = kg*16 + mt ; dst(u4) = mat*8192 + f*32 + lane.
// ---------------------------------------------------------------------------
__global__ void prepack_kernel(const float* sW2, const float* sW3, const float* sW4,
                               const float* tW2, const float* tW3, const float* tW4) {
    int idx = blockIdx.x * blockDim.x + threadIdx.x;
    if (idx >= NMAT * 8192) return;
    int lane = idx & 31;
    int mt   = (idx >> 5) & 15;
    int kg   = (idx >> 9) & 15;
    int mat  = idx >> 13;

    int st = mat / 18, rem = mat % 18, l = rem / 3, g = rem % 3;
    const float* src;
    switch (st * 3 + g) {
        case 0: src = sW2; break;
        case 1: src = sW3; break;
        case 2: src = sW4; break;
        case 3: src = tW2; break;
        case 4: src = tW3; break;
        default: src = tW4; break;
    }
    src += l * 65536;

    int v = lane & 3, mlow = lane >> 2;
    int kb = kg * 16;
    int nb = mt * 16;

    uint4 o;
    o.x = h2u(src[(kb + v)     * 256 + nb + mlow],     src[(kb + v + 8)  * 256 + nb + mlow]);
    o.y = h2u(src[(kb + v)     * 256 + nb + mlow + 8], src[(kb + v + 8)  * 256 + nb + mlow + 8]);
    o.z = h2u(src[(kb + v + 4) * 256 + nb + mlow],     src[(kb + v + 12) * 256 + nb + mlow]);
    o.w = h2u(src[(kb + v + 4) * 256 + nb + mlow + 8], src[(kb + v + 12) * 256 + nb + mlow + 8]);

    *((uint4*)g_wpack + (size_t)mat * 8192 + (kg * 16 + mt) * 32 + lane) = o;
}

// ---------------------------------------------------------------------------
// prepack phase params: 48 phases x 512 floats (same as R14).
// ---------------------------------------------------------------------------
__global__ void prepack_params(const float* sW1, const float* sB1, const float* sB2,
                               const float* sB3, const float* sB4, const float* sW5,
                               const float* tW1, const float* tB1, const float* tB2,
                               const float* tB3, const float* tB4, const float* tW5) {
    int idx = blockIdx.x * blockDim.x + threadIdx.x;
    if (idx >= NPHASE * 512) return;
    int p = idx >> 9, j = idx & 511;
    int blk = p >> 2, within = p & 3;
    int net = blk & 1, li = 5 - (blk >> 1);
    int cdim = (li & 1) ? 0 : 1, other = 1 - cdim;
    const float *W1, *B1, *B2, *B3, *B4, *W5;
    if (net == 0) { W1 = sW1; B1 = sB1; B2 = sB2; B3 = sB3; B4 = sB4; W5 = sW5; }
    else          { W1 = tW1; B1 = tB1; B2 = tB2; B3 = tB3; B4 = tB4; W5 = tW5; }
    float val = 0.f;
    if (within == 0)      val = (j < 256) ? W1[li * 512 + cdim * 256 + j]
                                          : B1[li * 256 + (j - 256)];
    else if (within == 1) { if (j < 256) val = B2[li * 256 + j]; }
    else if (within == 2) { if (j < 256) val = B3[li * 256 + j]; }
    else                  val = (j < 256) ? B4[li * 256 + j]
                                          : W5[li * 512 + (j - 256) * 2 + other];
    g_pb[p * 512 + j] = val;
}

// ---------------------------------------------------------------------------
__global__ void __launch_bounds__(NTHR, 2)
realnvp_kernel(const float* __restrict__ X,
               const float* __restrict__ sB5, const float* __restrict__ tB5,
               float* __restrict__ out) {
    extern __shared__ char base[];
    uint32_t* actu = (uint32_t*)(base + OFF_ACT);     // half2 words [row][STR2]
    float*    pbf  = (float*)(base + OFF_PBUF);       // [2][512] phase params
    float*    xv   = (float*)(base + OFF_XV);
    float*    pp   = (float*)(base + OFF_PP);         // [4][64]
    float*    sarr = (float*)(base + OFF_SARR);
    float*    tarr = (float*)(base + OFF_TARR);
    uint32_t  pbuf_sh = (uint32_t)__cvta_generic_to_shared(base + OFF_PBUF);

    int tid  = threadIdx.x;
    int wid  = tid >> 5, lane = tid & 31;     // wid = feature tile of 64 (0..3)
    int u    = lane >> 2;                     // 0..7
    int v    = lane & 3;                      // 0..3
    int gbase = blockIdx.x * MT;

    // hoisted loop-invariant bases
    const uint32_t* actu_b = actu + v * STR2 + u;                    // B-frag base
    const uint4* wbase = (const uint4*)g_wpack + (wid * 4) * 32 + lane; // A-frag base

    // ---- phase-param prefetch: 2KB into pbuf[(p&1)], own commit group ----
    auto pf_params = [&](int p) {
        if (p < NPHASE)
            cpasync16(pbuf_sh + (uint32_t)(p & 1) * 2048 + tid * 16,
                      g_pb + p * 512 + tid * 4);
        asm volatile("cp.async.commit_group;");
    };

    float ldet = 0.f;
    if (tid < MT) {
        float2 xx = *(const float2*)&X[(gbase + tid) * 2];
        xv[tid * 2 + 0] = logf(xx.x / (1.f - xx.x));
        xv[tid * 2 + 1] = logf(xx.y / (1.f - xx.y));
    }

    pf_params(0);
    asm volatile("cp.async.wait_group 0;");
    __syncthreads();     // phase-0 params + xv visible

    // ---- layer0: thread = one k-pair row (128 rows), 64 samples each ----
    auto layer0 = [&](int ph, int cdim) {
        pf_params(ph + 1);               // safe: all threads past previous phase
        const float* pb = pbf + (ph & 1) * 512;
        int r = tid;
        int k0 = ((r >> 3) << 4) + (r & 7), k1 = k0 + 8;
        float w0 = pb[k0],  bb0 = pb[256 + k0];
        float w1v = pb[k1], bb1 = pb[256 + k1];
#pragma unroll 4
        for (int i = 0; i < 16; i++) {
            uint4 wrds;
            int s = i * 4;
            float x0 = xv[(s + 0) * 2 + cdim], x1 = xv[(s + 1) * 2 + cdim];
            float x2 = xv[(s + 2) * 2 + cdim], x3 = xv[(s + 3) * 2 + cdim];
            wrds.x = h2u(fmaxf(fmaf(x0, w0, bb0), 0.f), fmaxf(fmaf(x0, w1v, bb1), 0.f));
            wrds.y = h2u(fmaxf(fmaf(x1, w0, bb0), 0.f), fmaxf(fmaf(x1, w1v, bb1), 0.f));
            wrds.z = h2u(fmaxf(fmaf(x2, w0, bb0), 0.f), fmaxf(fmaf(x2, w1v, bb1), 0.f));
            wrds.w = h2u(fmaxf(fmaf(x3, w0, bb0), 0.f), fmaxf(fmaf(x3, w1v, bb1), 0.f));
            *(uint4*)&actu[r * STR2 + s] = wrds;
        }
        // no trailing sync: next gemm's act-ready sync covers visibility
    };

    // ---- one 64x256 @ 256x256 GEMM; A-frags via LDG (L1/L2), depth-2 pipe ----
    auto gemm = [&](int mat, int ph, bool fuse, float b5, bool is_s) {
        const float* pb = pbf + (ph & 1) * 512;
        const uint4* abase = wbase + (size_t)mat * 8192;

        float acc[4][8][4];
#pragma unroll
        for (int a = 0; a < 4; a++)
#pragma unroll
            for (int b = 0; b < 8; b++)
#pragma unroll
                for (int q = 0; q < 4; q++) acc[a][b][q] = 0.f;

        uint4 af[3][4];
        // preload kg=0,1 BEFORE the act barrier (weights are independent)
#pragma unroll
        for (int mf = 0; mf < 4; mf++) af[0][mf] = __ldg(abase + 0 * 512 + mf * 32);
#pragma unroll
        for (int mf = 0; mf < 4; mf++) af[1][mf] = __ldg(abase + 1 * 512 + mf * 32);

        asm volatile("cp.async.wait_group 0;");   // this phase's params arrived
        __syncthreads();                          // act ready; params visible
        pf_params(ph + 1);

#pragma unroll
        for (int kg = 0; kg < 16; kg++) {
            int cur = kg % 3;
            if (kg < 14) {
                int nx = (kg + 2) % 3;
#pragma unroll
                for (int mf = 0; mf < 4; mf++)
                    af[nx][mf] = __ldg(abase + (kg + 2) * 512 + mf * 32);
            }
            const uint32_t* p0 = actu_b + kg * 8 * STR2;
            uint32_t b0[8], b1[8];
#pragma unroll
            for (int nf = 0; nf < 8; nf++) {
                b0[nf] = p0[nf * 8];
                b1[nf] = p0[4 * STR2 + nf * 8];
            }
#pragma unroll
            for (int mf = 0; mf < 4; mf++)
#pragma unroll
                for (int nf = 0; nf < 8; nf++)
                    mma_f16(acc[mf][nf], af[cur][mf], b0[nf], b1[nf]);
        }
        __syncthreads();                 // all reads of act done before overwrite

        if (!fuse) {
            // bias + relu + fp16 pair store; row = (wid*4+mf)*8+u holds (f0, f0+8)
#pragma unroll
            for (int mf = 0; mf < 4; mf++) {
                int f0 = wid * 64 + mf * 16 + u;
                int row = (wid * 4 + mf) * 8 + u;
                float bx = pb[f0], by = pb[f0 + 8];
#pragma unroll
                for (int nf = 0; nf < 8; nf++) {
                    int s0 = nf * 8 + v * 2;
                    uint2 wr;
                    wr.x = h2u(fmaxf(acc[mf][nf][0] + bx, 0.f),
                               fmaxf(acc[mf][nf][2] + by, 0.f));
                    wr.y = h2u(fmaxf(acc[mf][nf][1] + bx, 0.f),
                               fmaxf(acc[mf][nf][3] + by, 0.f));
                    *(uint2*)&actu[row * STR2 + s0] = wr;
                }
            }
            // no trailing sync: next gemm's act-ready sync covers visibility
        } else {
            // fused H->1 dot: p[s] = sum_f relu(acc+bias) * w5[f]
            float p[8][2];
#pragma unroll
            for (int nf = 0; nf < 8; nf++) { p[nf][0] = 0.f; p[nf][1] = 0.f; }
#pragma unroll
            for (int mf = 0; mf < 4; mf++) {
                int f0 = wid * 64 + mf * 16 + u;
                float bx = pb[f0],       by = pb[f0 + 8];
                float wa = pb[256 + f0], wb5 = pb[256 + f0 + 8];
#pragma unroll
                for (int nf = 0; nf < 8; nf++) {
                    float v0 = fmaxf(acc[mf][nf][0] + bx, 0.f);
                    float v1 = fmaxf(acc[mf][nf][1] + bx, 0.f);
                    float v2 = fmaxf(acc[mf][nf][2] + by, 0.f);
                    float v3 = fmaxf(acc[mf][nf][3] + by, 0.f);
                    p[nf][0] = fmaf(v0, wa, fmaf(v2, wb5, p[nf][0]));
                    p[nf][1] = fmaf(v1, wa, fmaf(v3, wb5, p[nf][1]));
                }
            }
#pragma unroll
            for (int nf = 0; nf < 8; nf++) {
#pragma unroll
                for (int j = 0; j < 2; j++) {
                    float t = p[nf][j];
                    t += __shfl_down_sync(0xffffffffu, t, 16);
                    t += __shfl_down_sync(0xffffffffu, t, 8);
                    t += __shfl_down_sync(0xffffffffu, t, 4);
                    if (lane < 4)
                        pp[wid * 64 + nf * 8 + lane * 2 + j] = t;
                }
            }
            __syncthreads();
            if (tid < MT) {
                float o = pp[tid] + pp[64 + tid] + pp[128 + tid] + pp[192 + tid] + b5;
                if (is_s) sarr[tid] = tanhf(o);
                else      tarr[tid] = o;
            }
        }
    };

    // ---- main flow: 6 coupling layers, reversed ----
    int ph = 0;
    for (int i = 5; i >= 0; i--) {
        int cdim = (i & 1) ? 0 : 1;
        int other = 1 - cdim;
        float b5s = sB5[i * 2 + other];
        float b5t = tB5[i * 2 + other];

        layer0(ph++, cdim);
        gemm((0 * 6 + i) * 3 + 0, ph++, false, 0.f, false);
        gemm((0 * 6 + i) * 3 + 1, ph++, false, 0.f, false);
        gemm((0 * 6 + i) * 3 + 2, ph++, true, b5s, true);

        layer0(ph++, cdim);
        gemm((1 * 6 + i) * 3 + 0, ph++, false, 0.f, false);
        gemm((1 * 6 + i) * 3 + 1, ph++, false, 0.f, false);
        gemm((1 * 6 + i) * 3 + 2, ph++, true, b5t, false);

        // coupling update (same-tid as sarr/tarr writers; no sync needed)
        if (tid < MT) {
            float sv = sarr[tid], tv = tarr[tid];
            xv[tid * 2 + other] = (xv[tid * 2 + other] - tv) * expf(-sv);
            ldet -= sv;
        }
        __syncthreads();    // xv visible to next layer0 / output
    }

    if (tid < MT) {
        int g = gbase + tid;
        float2 o;
        o.x = 1.f / (1.f + expf(-xv[tid * 2 + 0]));
        o.y = 1.f / (1.f + expf(-xv[tid * 2 + 1]));
        *(float2*)&out[g * 2] = o;
        out[2 * BSZ + g] = ldet;
    }
    asm volatile("cp.async.wait_group 0;");
}

// ---------------------------------------------------------------------------
extern "C" void kernel_launch(void* const* d_in, const int* in_sizes, int n_in,
                              void* d_out, int out_size) {
    const float* X   = (const float*)d_in[0];
    const float* sW1 = (const float*)d_in[1];
    const float* sB1 = (const float*)d_in[2];
    const float* sW2 = (const float*)d_in[3];
    const float* sB2 = (const float*)d_in[4];
    const float* sW3 = (const float*)d_in[5];
    const float* sB3 = (const float*)d_in[6];
    const float* sW4 = (const float*)d_in[7];
    const float* sB4 = (const float*)d_in[8];
    const float* sW5 = (const float*)d_in[9];
    const float* sB5 = (const float*)d_in[10];
    const float* tW1 = (const float*)d_in[11];
    const float* tB1 = (const float*)d_in[12];
    const float* tW2 = (const float*)d_in[13];
    const float* tB2 = (const float*)d_in[14];
    const float* tW3 = (const float*)d_in[15];
    const float* tB3 = (const float*)d_in[16];
    const float* tW4 = (const float*)d_in[17];
    const float* tB4 = (const float*)d_in[18];
    const float* tW5 = (const float*)d_in[19];
    const float* tB5 = (const float*)d_in[20];

    cudaFuncSetAttribute(realnvp_kernel, cudaFuncAttributeMaxDynamicSharedMemorySize,
                         SMEM_DYN);

    prepack_kernel<<<(NMAT * 8192 + 255) / 256, 256>>>(sW2, sW3, sW4, tW2, tW3, tW4);
    prepack_params<<<(NPHASE * 512 + 255) / 256, 256>>>(
        sW1, sB1, sB2, sB3, sB4, sW5, tW1, tB1, tB2, tB3, tB4, tW5);
    realnvp_kernel<<<BSZ / MT, NTHR, SMEM_DYN>>>(X, sB5, tB5, (float*)d_out);
}

// round 16
// speedup vs baseline: 1.2402x; 1.0099x over previous
#include <cuda_runtime.h>
#include <cuda_fp16.h>
#include <cstdint>

#define NTHR 128
#define MT 64
#define BSZ 131072
#define NMAT 36
#define NPHASE 48
#define STR2 72              // half2 words per act row; 72 mod 32 = 8 -> conflict-free

// smem byte offsets (double-buffered act, no weight ring)
#define OFF_ACT0 0                      // 128 rows x 72 words x 4B = 36864
#define OFF_ACT1 36864
#define OFF_PBUF 73728                  // 2 x 512 floats (phase-param ping-pong)
#define OFF_XV   77824                  // 64 x 2 floats
#define OFF_PP   78336                  // 4 x 64 floats
#define OFF_SARR 79360
#define OFF_TARR 79616
#define SMEM_DYN 79872

__device__ __half g_wpack[NMAT * 65536];
__device__ float  g_pb[NPHASE * 512];   // per-phase params (prepacked)

// ---------------------------------------------------------------------------
__device__ __forceinline__ void cpasync16(uint32_t dst, const void* src) {
    asm volatile("cp.async.cg.shared.global [%0], [%1], 16;" :: "r"(dst), "l"(src));
}
__device__ __forceinline__ void mma_f16(float acc[4], uint4 a, uint32_t b0, uint32_t b1) {
    asm volatile(
        "mma.sync.aligned.m16n8k16.row.col.f32.f16.f16.f32 "
        "{%0,%1,%2,%3}, {%4,%5,%6,%7}, {%8,%9}, {%0,%1,%2,%3};"
        : "+f"(acc[0]), "+f"(acc[1]), "+f"(acc[2]), "+f"(acc[3])
        : "r"(a.x), "r"(a.y), "r"(a.z), "r"(a.w), "r"(b0), "r"(b1));
}
__device__ __forceinline__ uint32_t h2u(float lo, float hi) {
    __half2 h = __floats2half2_rn(lo, hi);
    return *(uint32_t*)&h;
}

// ---------------------------------------------------------------------------
// prepack weights: W[k][n] fp32 -> fp16, A-fragment order for m16n8k16 with
// k-permutation kappa (pairs (j, j+8) within each 16-block).
// Flat layout: frag f = kg*16 + mt ; dst(u4) = mat*8192 + f*32 + lane.
// ---------------------------------------------------------------------------
__global__ void prepack_kernel(const float* sW2, const float* sW3, const float* sW4,
                               const float* tW2, const float* tW3, const float* tW4) {
    int idx = blockIdx.x * blockDim.x + threadIdx.x;
    if (idx >= NMAT * 8192) return;
    int lane = idx & 31;
    int mt   = (idx >> 5) & 15;
    int kg   = (idx >> 9) & 15;
    int mat  = idx >> 13;

    int st = mat / 18, rem = mat % 18, l = rem / 3, g = rem % 3;
    const float* src;
    switch (st * 3 + g) {
        case 0: src = sW2; break;
        case 1: src = sW3; break;
        case 2: src = sW4; break;
        case 3: src = tW2; break;
        case 4: src = tW3; break;
        default: src = tW4; break;
    }
    src += l * 65536;

    int v = lane & 3, mlow = lane >> 2;
    int kb = kg * 16;
    int nb = mt * 16;

    uint4 o;
    o.x = h2u(src[(kb + v)     * 256 + nb + mlow],     src[(kb + v + 8)  * 256 + nb + mlow]);
    o.y = h2u(src[(kb + v)     * 256 + nb + mlow + 8], src[(kb + v + 8)  * 256 + nb + mlow + 8]);
    o.z = h2u(src[(kb + v + 4) * 256 + nb + mlow],     src[(kb + v + 12) * 256 + nb + mlow]);
    o.w = h2u(src[(kb + v + 4) * 256 + nb + mlow + 8], src[(kb + v + 12) * 256 + nb + mlow + 8]);

    *((uint4*)g_wpack + (size_t)mat * 8192 + (kg * 16 + mt) * 32 + lane) = o;
}

// ---------------------------------------------------------------------------
// prepack phase params: 48 phases x 512 floats (same as R15).
// ---------------------------------------------------------------------------
__global__ void prepack_params(const float* sW1, const float* sB1, const float* sB2,
                               const float* sB3, const float* sB4, const float* sW5,
                               const float* tW1, const float* tB1, const float* tB2,
                               const float* tB3, const float* tB4, const float* tW5) {
    int idx = blockIdx.x * blockDim.x + threadIdx.x;
    if (idx >= NPHASE * 512) return;
    int p = idx >> 9, j = idx & 511;
    int blk = p >> 2, within = p & 3;
    int net = blk & 1, li = 5 - (blk >> 1);
    int cdim = (li & 1) ? 0 : 1, other = 1 - cdim;
    const float *W1, *B1, *B2, *B3, *B4, *W5;
    if (net == 0) { W1 = sW1; B1 = sB1; B2 = sB2; B3 = sB3; B4 = sB4; W5 = sW5; }
    else          { W1 = tW1; B1 = tB1; B2 = tB2; B3 = tB3; B4 = tB4; W5 = tW5; }
    float val = 0.f;
    if (within == 0)      val = (j < 256) ? W1[li * 512 + cdim * 256 + j]
                                          : B1[li * 256 + (j - 256)];
    else if (within == 1) { if (j < 256) val = B2[li * 256 + j]; }
    else if (within == 2) { if (j < 256) val = B3[li * 256 + j]; }
    else                  val = (j < 256) ? B4[li * 256 + j]
                                          : W5[li * 512 + (j - 256) * 2 + other];
    g_pb[p * 512 + j] = val;
}

// ---------------------------------------------------------------------------
__global__ void __launch_bounds__(NTHR, 2)
realnvp_kernel(const float* __restrict__ X,
               const float* __restrict__ sB5, const float* __restrict__ tB5,
               float* __restrict__ out) {
    extern __shared__ char base[];
    uint32_t* act0 = (uint32_t*)(base + OFF_ACT0);    // half2 words [row][STR2]
    uint32_t* act1 = (uint32_t*)(base + OFF_ACT1);
    float*    pbf  = (float*)(base + OFF_PBUF);       // [2][512] phase params
    float*    xv   = (float*)(base + OFF_XV);
    float*    pp   = (float*)(base + OFF_PP);         // [4][64]
    float*    sarr = (float*)(base + OFF_SARR);
    float*    tarr = (float*)(base + OFF_TARR);
    uint32_t  pbuf_sh = (uint32_t)__cvta_generic_to_shared(base + OFF_PBUF);

    int tid  = threadIdx.x;
    int wid  = tid >> 5, lane = tid & 31;     // wid = feature tile of 64 (0..3)
    int u    = lane >> 2;                     // 0..7
    int v    = lane & 3;                      // 0..3
    int gbase = blockIdx.x * MT;

    const uint4* wbase = (const uint4*)g_wpack + (wid * 4) * 32 + lane; // A-frag base

    // ---- phase-param prefetch: 2KB into pbuf[(p&1)], own commit group ----
    auto pf_params = [&](int p) {
        if (p < NPHASE)
            cpasync16(pbuf_sh + (uint32_t)(p & 1) * 2048 + tid * 16,
                      g_pb + p * 512 + tid * 4);
        asm volatile("cp.async.commit_group;");
    };

    float ldet = 0.f;
    if (tid < MT) {
        float2 xx = *(const float2*)&X[(gbase + tid) * 2];
        xv[tid * 2 + 0] = logf(xx.x / (1.f - xx.x));
        xv[tid * 2 + 1] = logf(xx.y / (1.f - xx.y));
    }

    pf_params(0);
    asm volatile("cp.async.wait_group 0;");
    __syncthreads();     // phase-0 params + xv visible

    // ---- layer0: thread = one k-pair row (128 rows) -> actw; no barrier ----
    auto layer0 = [&](int ph, int cdim, uint32_t* actw) {
        pf_params(ph + 1);               // safe: all threads past previous phase
        const float* pb = pbf + (ph & 1) * 512;
        int r = tid;
        int k0 = ((r >> 3) << 4) + (r & 7), k1 = k0 + 8;
        float w0 = pb[k0],  bb0 = pb[256 + k0];
        float w1v = pb[k1], bb1 = pb[256 + k1];
#pragma unroll 4
        for (int i = 0; i < 16; i++) {
            uint4 wrds;
            int s = i * 4;
            float x0 = xv[(s + 0) * 2 + cdim], x1 = xv[(s + 1) * 2 + cdim];
            float x2 = xv[(s + 2) * 2 + cdim], x3 = xv[(s + 3) * 2 + cdim];
            wrds.x = h2u(fmaxf(fmaf(x0, w0, bb0), 0.f), fmaxf(fmaf(x0, w1v, bb1), 0.f));
            wrds.y = h2u(fmaxf(fmaf(x1, w0, bb0), 0.f), fmaxf(fmaf(x1, w1v, bb1), 0.f));
            wrds.z = h2u(fmaxf(fmaf(x2, w0, bb0), 0.f), fmaxf(fmaf(x2, w1v, bb1), 0.f));
            wrds.w = h2u(fmaxf(fmaf(x3, w0, bb0), 0.f), fmaxf(fmaf(x3, w1v, bb1), 0.f));
            *(uint4*)&actw[r * STR2 + s] = wrds;
        }
        // next gemm's top sync publishes actw
    };

    // ---- one 64x256 @ 256x256 GEMM; reads actr, epilogue writes actw ----
    // ONE barrier per GEMM (top). A-frags via LDG depth-2 pipe.
    auto gemm = [&](int mat, int ph, const uint32_t* actr, uint32_t* actw,
                    bool fuse, float b5, bool is_s) {
        const float* pb = pbf + (ph & 1) * 512;
        const uint4* abase = wbase + (size_t)mat * 8192;
        const uint32_t* actu_rb = actr + v * STR2 + u;

        float acc[4][8][4];
#pragma unroll
        for (int a = 0; a < 4; a++)
#pragma unroll
            for (int b = 0; b < 8; b++)
#pragma unroll
                for (int q = 0; q < 4; q++) acc[a][b][q] = 0.f;

        uint4 af[3][4];
        // preload kg=0,1 BEFORE the act barrier (weights independent of act)
#pragma unroll
        for (int mf = 0; mf < 4; mf++) af[0][mf] = __ldg(abase + 0 * 512 + mf * 32);
#pragma unroll
        for (int mf = 0; mf < 4; mf++) af[1][mf] = __ldg(abase + 1 * 512 + mf * 32);

        asm volatile("cp.async.wait_group 0;");   // this phase's params arrived
        __syncthreads();                          // actr ready; params visible
        pf_params(ph + 1);

#pragma unroll
        for (int kg = 0; kg < 16; kg++) {
            int cur = kg % 3;
            if (kg < 14) {
                int nx = (kg + 2) % 3;
#pragma unroll
                for (int mf = 0; mf < 4; mf++)
                    af[nx][mf] = __ldg(abase + (kg + 2) * 512 + mf * 32);
            }
            const uint32_t* p0 = actu_rb + kg * 8 * STR2;
            uint32_t b0[8], b1[8];
#pragma unroll
            for (int nf = 0; nf < 8; nf++) {
                b0[nf] = p0[nf * 8];
                b1[nf] = p0[4 * STR2 + nf * 8];
            }
#pragma unroll
            for (int mf = 0; mf < 4; mf++)
#pragma unroll
                for (int nf = 0; nf < 8; nf++)
                    mma_f16(acc[mf][nf], af[cur][mf], b0[nf], b1[nf]);
        }
        // NO bottom barrier: epilogue writes actw (!= actr), stragglers unharmed

        if (!fuse) {
            // bias + relu + fp16 pair store; row = (wid*4+mf)*8+u holds (f0, f0+8)
#pragma unroll
            for (int mf = 0; mf < 4; mf++) {
                int f0 = wid * 64 + mf * 16 + u;
                int row = (wid * 4 + mf) * 8 + u;
                float bx = pb[f0], by = pb[f0 + 8];
#pragma unroll
                for (int nf = 0; nf < 8; nf++) {
                    int s0 = nf * 8 + v * 2;
                    uint2 wr;
                    wr.x = h2u(fmaxf(acc[mf][nf][0] + bx, 0.f),
                               fmaxf(acc[mf][nf][2] + by, 0.f));
                    wr.y = h2u(fmaxf(acc[mf][nf][1] + bx, 0.f),
                               fmaxf(acc[mf][nf][3] + by, 0.f));
                    *(uint2*)&actw[row * STR2 + s0] = wr;
                }
            }
        } else {
            // fused H->1 dot: p[s] = sum_f relu(acc+bias) * w5[f]
            float p[8][2];
#pragma unroll
            for (int nf = 0; nf < 8; nf++) { p[nf][0] = 0.f; p[nf][1] = 0.f; }
#pragma unroll
            for (int mf = 0; mf < 4; mf++) {
                int f0 = wid * 64 + mf * 16 + u;
                float bx = pb[f0],       by = pb[f0 + 8];
                float wa = pb[256 + f0], wb5 = pb[256 + f0 + 8];
#pragma unroll
                for (int nf = 0; nf < 8; nf++) {
                    float v0 = fmaxf(acc[mf][nf][0] + bx, 0.f);
                    float v1 = fmaxf(acc[mf][nf][1] + bx, 0.f);
                    float v2 = fmaxf(acc[mf][nf][2] + by, 0.f);
                    float v3 = fmaxf(acc[mf][nf][3] + by, 0.f);
                    p[nf][0] = fmaf(v0, wa, fmaf(v2, wb5, p[nf][0]));
                    p[nf][1] = fmaf(v1, wa, fmaf(v3, wb5, p[nf][1]));
                }
            }
#pragma unroll
            for (int nf = 0; nf < 8; nf++) {
#pragma unroll
                for (int j = 0; j < 2; j++) {
                    float t = p[nf][j];
                    t += __shfl_down_sync(0xffffffffu, t, 16);
                    t += __shfl_down_sync(0xffffffffu, t, 8);
                    t += __shfl_down_sync(0xffffffffu, t, 4);
                    if (lane < 4)
                        pp[wid * 64 + nf * 8 + lane * 2 + j] = t;
                }
            }
            asm volatile("cp.async.wait_group 0;");  // next phase's params done...
            __syncthreads();                         // ...and published to all
            if (tid < MT) {
                float o = pp[tid] + pp[64 + tid] + pp[128 + tid] + pp[192 + tid] + b5;
                if (is_s) sarr[tid] = tanhf(o);
                else      tarr[tid] = o;
            }
        }
    };

    // ---- main flow: 6 coupling layers, reversed; act ping-pongs 0->1->0 ----
    int ph = 0;
    for (int i = 5; i >= 0; i--) {
        int cdim = (i & 1) ? 0 : 1;
        int other = 1 - cdim;
        float b5s = sB5[i * 2 + other];
        float b5t = tB5[i * 2 + other];

        layer0(ph++, cdim, act0);
        gemm((0 * 6 + i) * 3 + 0, ph++, act0, act1, false, 0.f, false);
        gemm((0 * 6 + i) * 3 + 1, ph++, act1, act0, false, 0.f, false);
        gemm((0 * 6 + i) * 3 + 2, ph++, act0, act1, true, b5s, true);

        layer0(ph++, cdim, act0);
        gemm((1 * 6 + i) * 3 + 0, ph++, act0, act1, false, 0.f, false);
        gemm((1 * 6 + i) * 3 + 1, ph++, act1, act0, false, 0.f, false);
        gemm((1 * 6 + i) * 3 + 2, ph++, act0, act1, true, b5t, false);

        // coupling update (same-tid as sarr/tarr writers; no sync needed)
        if (tid < MT) {
            float sv = sarr[tid], tv = tarr[tid];
            xv[tid * 2 + other] = (xv[tid * 2 + other] - tv) * expf(-sv);
            ldet -= sv;
        }
        __syncthreads();    // xv visible to next layer0 / output
    }

    if (tid < MT) {
        int g = gbase + tid;
        float2 o;
        o.x = 1.f / (1.f + expf(-xv[tid * 2 + 0]));
        o.y = 1.f / (1.f + expf(-xv[tid * 2 + 1]));
        *(float2*)&out[g * 2] = o;
        out[2 * BSZ + g] = ldet;
    }
    asm volatile("cp.async.wait_group 0;");
}

// ---------------------------------------------------------------------------
extern "C" void kernel_launch(void* const* d_in, const int* in_sizes, int n_in,
                              void* d_out, int out_size) {
    const float* X   = (const float*)d_in[0];
    const float* sW1 = (const float*)d_in[1];
    const float* sB1 = (const float*)d_in[2];
    const float* sW2 = (const float*)d_in[3];
    const float* sB2 = (const float*)d_in[4];
    const float* sW3 = (const float*)d_in[5];
    const float* sB3 = (const float*)d_in[6];
    const float* sW4 = (const float*)d_in[7];
    const float* sB4 = (const float*)d_in[8];
    const float* sW5 = (const float*)d_in[9];
    const float* sB5 = (const float*)d_in[10];
    const float* tW1 = (const float*)d_in[11];
    const float* tB1 = (const float*)d_in[12];
    const float* tW2 = (const float*)d_in[13];
    const float* tB2 = (const float*)d_in[14];
    const float* tW3 = (const float*)d_in[15];
    const float* tB3 = (const float*)d_in[16];
    const float* tW4 = (const float*)d_in[17];
    const float* tB4 = (const float*)d_in[18];
    const float* tW5 = (const float*)d_in[19];
    const float* tB5 = (const float*)d_in[20];

    cudaFuncSetAttribute(realnvp_kernel, cudaFuncAttributeMaxDynamicSharedMemorySize,
                         SMEM_DYN);

    prepack_kernel<<<(NMAT * 8192 + 255) / 256, 256>>>(sW2, sW3, sW4, tW2, tW3, tW4);
    prepack_params<<<(NPHASE * 512 + 255) / 256, 256>>>(
        sW1, sB1, sB2, sB3, sB4, sW5, tW1, tB1, tB2, tB3, tB4, tW5);
    realnvp_kernel<<<BSZ / MT, NTHR, SMEM_DYN>>>(X, sB5, tB5, (float*)d_out);
}

// round 17
// speedup vs baseline: 6.9394x; 5.5952x over previous
#include <cuda_runtime.h>
#include <cuda_fp16.h>
#include <cstdint>

#define NTHR 128
#define MT 64
#define BSZ 131072
#define NMAT 36
#define NPHASE 48
#define STR2 72              // half2 words per act row; 72 mod 32 = 8 -> conflict-free
#define G 16384              // table resolution (exact MLP evals per layer per net)

// smem byte offsets for the tabulate kernel
#define OFF_ACT0 0                      // 128 rows x 72 words x 4B = 36864
#define OFF_ACT1 36864
#define OFF_PBUF 73728                  // 2 x 512 floats (phase-param ping-pong)
#define OFF_GV   77824                  // 64 grid values
#define OFF_PP   78080                  // 4 x 64 floats
#define OFF_SARR 79104
#define OFF_TARR 79360
#define SMEM_DYN 79616

__device__ __half  g_wpack[NMAT * 65536];
__device__ float   g_pb[NPHASE * 512];
__device__ float2  g_x[BSZ];
__device__ float   g_ldet[BSZ];
__device__ float   g_tabS[G];
__device__ float   g_tabT[G];
__device__ unsigned g_mm[14];           // [step][min,max] as ordered uints

// ---------------------------------------------------------------------------
__device__ __forceinline__ void cpasync16(uint32_t dst, const void* src) {
    asm volatile("cp.async.cg.shared.global [%0], [%1], 16;" :: "r"(dst), "l"(src));
}
__device__ __forceinline__ void mma_f16(float acc[4], uint4 a, uint32_t b0, uint32_t b1) {
    asm volatile(
        "mma.sync.aligned.m16n8k16.row.col.f32.f16.f16.f32 "
        "{%0,%1,%2,%3}, {%4,%5,%6,%7}, {%8,%9}, {%0,%1,%2,%3};"
        : "+f"(acc[0]), "+f"(acc[1]), "+f"(acc[2]), "+f"(acc[3])
        : "r"(a.x), "r"(a.y), "r"(a.z), "r"(a.w), "r"(b0), "r"(b1));
}
__device__ __forceinline__ uint32_t h2u(float lo, float hi) {
    __half2 h = __floats2half2_rn(lo, hi);
    return *(uint32_t*)&h;
}
__device__ __forceinline__ unsigned f2o(float f) {
    unsigned b = __float_as_uint(f);
    return (b & 0x80000000u) ? ~b : (b | 0x80000000u);
}
__device__ __forceinline__ float o2f(unsigned o) {
    return __uint_as_float((o & 0x80000000u) ? (o & 0x7fffffffu) : ~o);
}

// ---------------------------------------------------------------------------
// prepack weights (identical to R16): fp16 A-fragment order, kappa k-perm.
// ---------------------------------------------------------------------------
__global__ void prepack_kernel(const float* sW2, const float* sW3, const float* sW4,
                               const float* tW2, const float* tW3, const float* tW4) {
    int idx = blockIdx.x * blockDim.x + threadIdx.x;
    if (idx >= NMAT * 8192) return;
    int lane = idx & 31;
    int mt   = (idx >> 5) & 15;
    int kg   = (idx >> 9) & 15;
    int mat  = idx >> 13;

    int st = mat / 18, rem = mat % 18, l = rem / 3, g = rem % 3;
    const float* src;
    switch (st * 3 + g) {
        case 0: src = sW2; break;
        case 1: src = sW3; break;
        case 2: src = sW4; break;
        case 3: src = tW2; break;
        case 4: src = tW3; break;
        default: src = tW4; break;
    }
    src += l * 65536;

    int v = lane & 3, mlow = lane >> 2;
    int kb = kg * 16, nb = mt * 16;

    uint4 o;
    o.x = h2u(src[(kb + v)     * 256 + nb + mlow],     src[(kb + v + 8)  * 256 + nb + mlow]);
    o.y = h2u(src[(kb + v)     * 256 + nb + mlow + 8], src[(kb + v + 8)  * 256 + nb + mlow + 8]);
    o.z = h2u(src[(kb + v + 4) * 256 + nb + mlow],     src[(kb + v + 12) * 256 + nb + mlow]);
    o.w = h2u(src[(kb + v + 4) * 256 + nb + mlow + 8], src[(kb + v + 12) * 256 + nb + mlow + 8]);

    *((uint4*)g_wpack + (size_t)mat * 8192 + (kg * 16 + mt) * 32 + lane) = o;
}

// ---------------------------------------------------------------------------
// prepack phase params (identical to R16): 48 phases x 512 floats.
// ---------------------------------------------------------------------------
__global__ void prepack_params(const float* sW1, const float* sB1, const float* sB2,
                               const float* sB3, const float* sB4, const float* sW5,
                               const float* tW1, const float* tB1, const float* tB2,
                               const float* tB3, const float* tB4, const float* tW5) {
    int idx = blockIdx.x * blockDim.x + threadIdx.x;
    if (idx >= NPHASE * 512) return;
    int p = idx >> 9, j = idx & 511;
    int blk = p >> 2, within = p & 3;
    int net = blk & 1, li = 5 - (blk >> 1);
    int cdim = (li & 1) ? 0 : 1, other = 1 - cdim;
    const float *W1, *B1, *B2, *B3, *B4, *W5;
    if (net == 0) { W1 = sW1; B1 = sB1; B2 = sB2; B3 = sB3; B4 = sB4; W5 = sW5; }
    else          { W1 = tW1; B1 = tB1; B2 = tB2; B3 = tB3; B4 = tB4; W5 = tW5; }
    float val = 0.f;
    if (within == 0)      val = (j < 256) ? W1[li * 512 + cdim * 256 + j]
                                          : B1[li * 256 + (j - 256)];
    else if (within == 1) { if (j < 256) val = B2[li * 256 + j]; }
    else if (within == 2) { if (j < 256) val = B3[li * 256 + j]; }
    else                  val = (j < 256) ? B4[li * 256 + j]
                                          : W5[li * 512 + (j - 256) * 2 + other];
    g_pb[p * 512 + j] = val;
}

// ---------------------------------------------------------------------------
__global__ void reset_kernel() {
    int i = threadIdx.x;
    if (i < 7) { g_mm[i * 2] = 0xFFFFFFFFu; g_mm[i * 2 + 1] = 0u; }
}

// ---------------------------------------------------------------------------
// init: logit(X) -> g_x, ldet=0, min/max of dim0 -> g_mm[0]
// ---------------------------------------------------------------------------
__global__ void init_kernel(const float* __restrict__ X) {
    int idx = blockIdx.x * blockDim.x + threadIdx.x;
    float2 xx = ((const float2*)X)[idx];
    xx.x = logf(xx.x / (1.f - xx.x));
    xx.y = logf(xx.y / (1.f - xx.y));
    g_x[idx] = xx;
    g_ldet[idx] = 0.f;

    float mn = xx.x, mx = xx.x;
#pragma unroll
    for (int o = 16; o; o >>= 1) {
        mn = fminf(mn, __shfl_xor_sync(0xffffffffu, mn, o));
        mx = fmaxf(mx, __shfl_xor_sync(0xffffffffu, mx, o));
    }
    __shared__ float smn[16], smx[16];
    int lane = threadIdx.x & 31, wid = threadIdx.x >> 5;
    if (lane == 0) { smn[wid] = mn; smx[wid] = mx; }
    __syncthreads();
    if (threadIdx.x < 32) {
        mn = (threadIdx.x < 16) ? smn[threadIdx.x] : smn[0];
        mx = (threadIdx.x < 16) ? smx[threadIdx.x] : smx[0];
#pragma unroll
        for (int o = 8; o; o >>= 1) {
            mn = fminf(mn, __shfl_xor_sync(0xffffffffu, mn, o));
            mx = fmaxf(mx, __shfl_xor_sync(0xffffffffu, mx, o));
        }
        if (threadIdx.x == 0) {
            atomicMin(&g_mm[0], f2o(mn));
            atomicMax(&g_mm[1], f2o(mx));
        }
    }
}

// ---------------------------------------------------------------------------
// tabulate: evaluate S_i, T_i exactly (fp16 tensor cores) at 64 grid points
// per CTA; 256 CTAs cover G=16384. One coupling layer per launch.
// ---------------------------------------------------------------------------
__global__ void __launch_bounds__(NTHR, 2)
tab_kernel(int li, int step, const float* __restrict__ sB5,
           const float* __restrict__ tB5) {
    extern __shared__ char base[];
    uint32_t* act0 = (uint32_t*)(base + OFF_ACT0);
    uint32_t* act1 = (uint32_t*)(base + OFF_ACT1);
    float*    pbf  = (float*)(base + OFF_PBUF);
    float*    gvs  = (float*)(base + OFF_GV);
    float*    pp   = (float*)(base + OFF_PP);
    float*    sarr = (float*)(base + OFF_SARR);
    float*    tarr = (float*)(base + OFF_TARR);
    uint32_t  pbuf_sh = (uint32_t)__cvta_generic_to_shared(base + OFF_PBUF);

    int tid  = threadIdx.x;
    int wid  = tid >> 5, lane = tid & 31;
    int u    = lane >> 2;
    int v    = lane & 3;
    int other = (li & 1) ? 1 : 0;        // cdim=(li&1)?0:1 -> other=1-cdim
    int phb  = step * 8;

    const uint4* wbase = (const uint4*)g_wpack + (wid * 4) * 32 + lane;

    auto pf_params = [&](int p) {
        if (p < NPHASE)
            cpasync16(pbuf_sh + (uint32_t)(p & 1) * 2048 + tid * 16,
                      g_pb + p * 512 + tid * 4);
        asm volatile("cp.async.commit_group;");
    };

    // grid values for this CTA
    float lo = o2f(g_mm[step * 2]), hi = o2f(g_mm[step * 2 + 1]);
    float delta = (hi > lo) ? (hi - lo) / (float)(G - 1) : 0.f;
    if (tid < MT)
        gvs[tid] = lo + (float)(blockIdx.x * MT + tid) * delta;

    pf_params(phb);
    asm volatile("cp.async.wait_group 0;");
    __syncthreads();     // phase params + gvs visible

    auto layer0 = [&](int ph, uint32_t* actw) {
        pf_params(ph + 1);
        const float* pb = pbf + (ph & 1) * 512;
        int r = tid;
        int k0 = ((r >> 3) << 4) + (r & 7), k1 = k0 + 8;
        float w0 = pb[k0],  bb0 = pb[256 + k0];
        float w1v = pb[k1], bb1 = pb[256 + k1];
#pragma unroll 4
        for (int i = 0; i < 16; i++) {
            uint4 wrds;
            int s = i * 4;
            float x0 = gvs[s], x1 = gvs[s + 1], x2 = gvs[s + 2], x3 = gvs[s + 3];
            wrds.x = h2u(fmaxf(fmaf(x0, w0, bb0), 0.f), fmaxf(fmaf(x0, w1v, bb1), 0.f));
            wrds.y = h2u(fmaxf(fmaf(x1, w0, bb0), 0.f), fmaxf(fmaf(x1, w1v, bb1), 0.f));
            wrds.z = h2u(fmaxf(fmaf(x2, w0, bb0), 0.f), fmaxf(fmaf(x2, w1v, bb1), 0.f));
            wrds.w = h2u(fmaxf(fmaf(x3, w0, bb0), 0.f), fmaxf(fmaf(x3, w1v, bb1), 0.f));
            *(uint4*)&actw[r * STR2 + s] = wrds;
        }
    };

    auto gemm = [&](int mat, int ph, const uint32_t* actr, uint32_t* actw,
                    bool fuse, float b5, bool is_s) {
        const float* pb = pbf + (ph & 1) * 512;
        const uint4* abase = wbase + (size_t)mat * 8192;
        const uint32_t* actu_rb = actr + v * STR2 + u;

        float acc[4][8][4];
#pragma unroll
        for (int a = 0; a < 4; a++)
#pragma unroll
            for (int b = 0; b < 8; b++)
#pragma unroll
                for (int q = 0; q < 4; q++) acc[a][b][q] = 0.f;

        uint4 af[3][4];
#pragma unroll
        for (int mf = 0; mf < 4; mf++) af[0][mf] = __ldg(abase + 0 * 512 + mf * 32);
#pragma unroll
        for (int mf = 0; mf < 4; mf++) af[1][mf] = __ldg(abase + 1 * 512 + mf * 32);

        asm volatile("cp.async.wait_group 0;");
        __syncthreads();
        pf_params(ph + 1);

#pragma unroll
        for (int kg = 0; kg < 16; kg++) {
            int cur = kg % 3;
            if (kg < 14) {
                int nx = (kg + 2) % 3;
#pragma unroll
                for (int mf = 0; mf < 4; mf++)
                    af[nx][mf] = __ldg(abase + (kg + 2) * 512 + mf * 32);
            }
            const uint32_t* p0 = actu_rb + kg * 8 * STR2;
            uint32_t b0[8], b1[8];
#pragma unroll
            for (int nf = 0; nf < 8; nf++) {
                b0[nf] = p0[nf * 8];
                b1[nf] = p0[4 * STR2 + nf * 8];
            }
#pragma unroll
            for (int mf = 0; mf < 4; mf++)
#pragma unroll
                for (int nf = 0; nf < 8; nf++)
                    mma_f16(acc[mf][nf], af[cur][mf], b0[nf], b1[nf]);
        }

        if (!fuse) {
#pragma unroll
            for (int mf = 0; mf < 4; mf++) {
                int f0 = wid * 64 + mf * 16 + u;
                int row = (wid * 4 + mf) * 8 + u;
                float bx = pb[f0], by = pb[f0 + 8];
#pragma unroll
                for (int nf = 0; nf < 8; nf++) {
                    int s0 = nf * 8 + v * 2;
                    uint2 wr;
                    wr.x = h2u(fmaxf(acc[mf][nf][0] + bx, 0.f),
                               fmaxf(acc[mf][nf][2] + by, 0.f));
                    wr.y = h2u(fmaxf(acc[mf][nf][1] + bx, 0.f),
                               fmaxf(acc[mf][nf][3] + by, 0.f));
                    *(uint2*)&actw[row * STR2 + s0] = wr;
                }
            }
        } else {
            float p[8][2];
#pragma unroll
            for (int nf = 0; nf < 8; nf++) { p[nf][0] = 0.f; p[nf][1] = 0.f; }
#pragma unroll
            for (int mf = 0; mf < 4; mf++) {
                int f0 = wid * 64 + mf * 16 + u;
                float bx = pb[f0],       by = pb[f0 + 8];
                float wa = pb[256 + f0], wb5 = pb[256 + f0 + 8];
#pragma unroll
                for (int nf = 0; nf < 8; nf++) {
                    float v0 = fmaxf(acc[mf][nf][0] + bx, 0.f);
                    float v1 = fmaxf(acc[mf][nf][1] + bx, 0.f);
                    float v2 = fmaxf(acc[mf][nf][2] + by, 0.f);
                    float v3 = fmaxf(acc[mf][nf][3] + by, 0.f);
                    p[nf][0] = fmaf(v0, wa, fmaf(v2, wb5, p[nf][0]));
                    p[nf][1] = fmaf(v1, wa, fmaf(v3, wb5, p[nf][1]));
                }
            }
#pragma unroll
            for (int nf = 0; nf < 8; nf++) {
#pragma unroll
                for (int j = 0; j < 2; j++) {
                    float t = p[nf][j];
                    t += __shfl_down_sync(0xffffffffu, t, 16);
                    t += __shfl_down_sync(0xffffffffu, t, 8);
                    t += __shfl_down_sync(0xffffffffu, t, 4);
                    if (lane < 4)
                        pp[wid * 64 + nf * 8 + lane * 2 + j] = t;
                }
            }
            asm volatile("cp.async.wait_group 0;");
            __syncthreads();
            if (tid < MT) {
                float o = pp[tid] + pp[64 + tid] + pp[128 + tid] + pp[192 + tid] + b5;
                if (is_s) sarr[tid] = tanhf(o);
                else      tarr[tid] = o;
            }
        }
    };

    float b5s = sB5[li * 2 + other];
    float b5t = tB5[li * 2 + other];

    int ph = phb;
    layer0(ph++, act0);
    gemm((0 * 6 + li) * 3 + 0, ph++, act0, act1, false, 0.f, false);
    gemm((0 * 6 + li) * 3 + 1, ph++, act1, act0, false, 0.f, false);
    gemm((0 * 6 + li) * 3 + 2, ph++, act0, act1, true, b5s, true);

    layer0(ph++, act0);
    gemm((1 * 6 + li) * 3 + 0, ph++, act0, act1, false, 0.f, false);
    gemm((1 * 6 + li) * 3 + 1, ph++, act1, act0, false, 0.f, false);
    gemm((1 * 6 + li) * 3 + 2, ph++, act0, act1, true, b5t, false);

    // sarr/tarr[tid] were written by this same thread -> no sync needed
    if (tid < MT) {
        int j = blockIdx.x * MT + tid;
        g_tabS[j] = sarr[tid];
        g_tabT[j] = tarr[tid];
    }
    asm volatile("cp.async.wait_group 0;");
}

// ---------------------------------------------------------------------------
// map: per-sample table lookup + coupling update; min/max of updated dim.
// ---------------------------------------------------------------------------
__global__ void map_kernel(int step, int cdim, int islast, float* __restrict__ out) {
    int idx = blockIdx.x * blockDim.x + threadIdx.x;
    float lo = o2f(g_mm[step * 2]), hi = o2f(g_mm[step * 2 + 1]);
    float scale = (hi > lo) ? (float)(G - 1) / (hi - lo) : 0.f;

    float2 xx = g_x[idx];
    float uc = cdim ? xx.y : xx.x;
    float pos = (uc - lo) * scale;
    pos = fminf(fmaxf(pos, 0.f), (float)(G - 1));
    int j = min((int)pos, G - 2);
    float fr = pos - (float)j;
    float S0 = __ldg(&g_tabS[j]), S1 = __ldg(&g_tabS[j + 1]);
    float T0 = __ldg(&g_tabT[j]), T1 = __ldg(&g_tabT[j + 1]);
    float S = S0 + fr * (S1 - S0);
    float T = T0 + fr * (T1 - T0);

    float xo = cdim ? xx.x : xx.y;       // the 'other' dim
    xo = (xo - T) * expf(-S);
    if (cdim) xx.x = xo; else xx.y = xo;
    float ld = g_ldet[idx] - S;

    if (islast) {
        out[idx * 2]     = 1.f / (1.f + expf(-xx.x));
        out[idx * 2 + 1] = 1.f / (1.f + expf(-xx.y));
        out[2 * BSZ + idx] = ld;
        return;
    }
    g_x[idx] = xx;
    g_ldet[idx] = ld;

    // block reduce min/max of xo -> g_mm[step+1]
    float mn = xo, mx = xo;
#pragma unroll
    for (int o = 16; o; o >>= 1) {
        mn = fminf(mn, __shfl_xor_sync(0xffffffffu, mn, o));
        mx = fmaxf(mx, __shfl_xor_sync(0xffffffffu, mx, o));
    }
    __shared__ float smn[16], smx[16];
    int lane = threadIdx.x & 31, wid = threadIdx.x >> 5;
    if (lane == 0) { smn[wid] = mn; smx[wid] = mx; }
    __syncthreads();
    if (threadIdx.x < 32) {
        mn = (threadIdx.x < 16) ? smn[threadIdx.x] : smn[0];
        mx = (threadIdx.x < 16) ? smx[threadIdx.x] : smx[0];
#pragma unroll
        for (int o = 8; o; o >>= 1) {
            mn = fminf(mn, __shfl_xor_sync(0xffffffffu, mn, o));
            mx = fmaxf(mx, __shfl_xor_sync(0xffffffffu, mx, o));
        }
        if (threadIdx.x == 0) {
            atomicMin(&g_mm[(step + 1) * 2],     f2o(mn));
            atomicMax(&g_mm[(step + 1) * 2 + 1], f2o(mx));
        }
    }
}

// ---------------------------------------------------------------------------
extern "C" void kernel_launch(void* const* d_in, const int* in_sizes, int n_in,
                              void* d_out, int out_size) {
    const float* X   = (const float*)d_in[0];
    const float* sW1 = (const float*)d_in[1];
    const float* sB1 = (const float*)d_in[2];
    const float* sW2 = (const float*)d_in[3];
    const float* sB2 = (const float*)d_in[4];
    const float* sW3 = (const float*)d_in[5];
    const float* sB3 = (const float*)d_in[6];
    const float* sW4 = (const float*)d_in[7];
    const float* sB4 = (const float*)d_in[8];
    const float* sW5 = (const float*)d_in[9];
    const float* sB5 = (const float*)d_in[10];
    const float* tW1 = (const float*)d_in[11];
    const float* tB1 = (const float*)d_in[12];
    const float* tW2 = (const float*)d_in[13];
    const float* tB2 = (const float*)d_in[14];
    const float* tW3 = (const float*)d_in[15];
    const float* tB3 = (const float*)d_in[16];
    const float* tW4 = (const float*)d_in[17];
    const float* tB4 = (const float*)d_in[18];
    const float* tW5 = (const float*)d_in[19];
    const float* tB5 = (const float*)d_in[20];

    cudaFuncSetAttribute(tab_kernel, cudaFuncAttributeMaxDynamicSharedMemorySize,
                         SMEM_DYN);

    prepack_kernel<<<(NMAT * 8192 + 255) / 256, 256>>>(sW2, sW3, sW4, tW2, tW3, tW4);
    prepack_params<<<(NPHASE * 512 + 255) / 256, 256>>>(
        sW1, sB1, sB2, sB3, sB4, sW5, tW1, tB1, tB2, tB3, tB4, tW5);
    reset_kernel<<<1, 32>>>();
    init_kernel<<<BSZ / 512, 512>>>(X);

    int step = 0;
    for (int i = 5; i >= 0; i--) {
        int cdim = (i & 1) ? 0 : 1;
        tab_kernel<<<G / MT, NTHR, SMEM_DYN>>>(i, step, sB5, tB5);
        map_kernel<<<BSZ / 512, 512>>>(step, cdim, (i == 0) ? 1 : 0, (float*)d_out);
        step++;
    }
}